// round 10
// baseline (speedup 1.0000x reference)
#include <cuda_runtime.h>
#include <cuda_bf16.h>
#include <cooperative_groups.h>
#include <cstdint>

namespace cg = cooperative_groups;

#define NUM_C 1024
#define EMB   512
#define HID   512
#define BATCH 64
#define SEQ   512
#define M_ROWS (BATCH * SEQ)   // 32768
#define NROWS 2048             // distinct embedding rows

// ---------------------------------------------------------------------------
// Device scratch
// ---------------------------------------------------------------------------
__device__ float g_table[(size_t)NROWS * HID];    // 4 MB: emb@Wx^T + bx + bh
__device__ float g_hs   [(size_t)M_ROWS * HID];   // 64 MB: scan outputs

// ---------------------------------------------------------------------------
// f32x2 helpers
// ---------------------------------------------------------------------------
__device__ __forceinline__ void fma2(unsigned long long& acc,
                                     unsigned long long a, unsigned long long b) {
    asm("fma.rn.f32x2 %0, %1, %2, %0;" : "+l"(acc) : "l"(a), "l"(b));
}
__device__ __forceinline__ unsigned long long pk2(float lo, float hi) {
    unsigned long long r;
    asm("mov.b64 %0, {%1, %2};" : "=l"(r) : "f"(lo), "f"(hi));
    return r;
}
__device__ __forceinline__ unsigned long long dup2(float x) {
    unsigned long long r;
    asm("mov.b64 %0, {%1, %1};" : "=l"(r) : "f"(x));
    return r;
}
__device__ __forceinline__ void upk2(unsigned long long v, float& lo, float& hi) {
    asm("mov.b64 {%0, %1}, %2;" : "=f"(lo), "=f"(hi) : "l"(v));
}
__device__ __forceinline__ void add2(unsigned long long& acc, unsigned long long a) {
    asm("add.rn.f32x2 %0, %1, %2;" : "=l"(acc) : "l"(acc), "l"(a));
}
__device__ __forceinline__ void dupsplit(unsigned long long w,
                                         unsigned long long& a, unsigned long long& b) {
    asm("{\n\t.reg .b32 lo,hi;\n\t"
        "mov.b64 {lo,hi}, %2;\n\t"
        "mov.b64 %0, {lo,lo};\n\t"
        "mov.b64 %1, {hi,hi};\n\t}"
        : "=l"(a), "=l"(b) : "l"(w));
}

#define CLUSTER_ARRIVE() asm volatile("barrier.cluster.arrive.aligned;" ::: "memory")
#define CLUSTER_WAIT()   asm volatile("barrier.cluster.wait.aligned;"   ::: "memory")

// ---------------------------------------------------------------------------
// proj v2: table[m][n] = sum_e emb[m][e]*Wx_w[n][e] + Wx_b[n] + Wh_b[n]
// 512 threads, tile 128 rows x 64 cols, grid (8,16) = 128 CTAs.
// ---------------------------------------------------------------------------
__global__ __launch_bounds__(512, 2)
void proj_kernel(const float* __restrict__ emb,
                 const float* __restrict__ Wx_w,
                 const float* __restrict__ Wx_b,
                 const float* __restrict__ Wh_b) {
    __shared__ unsigned long long As2[8][128];   // dup'd a: (a,a)
    __shared__ float              Bs[8][64];

    const int tid  = threadIdx.x;
    const int row0 = blockIdx.y * 128;
    const int col0 = blockIdx.x * 64;

    const int tx = tid & 15;     // c-quad
    const int ty = tid >> 4;     // r-quad

    unsigned long long acc[4][2];
#pragma unroll
    for (int i = 0; i < 4; i++) { acc[i][0] = 0ull; acc[i][1] = 0ull; }

    const int a_r  = tid >> 1;
    const int a_kq = (tid & 1) * 4;
    const int b_c  = (tid - 256) >> 1;
    const int b_kq = (tid & 1) * 4;

    float4 pa = make_float4(0, 0, 0, 0), pb = make_float4(0, 0, 0, 0);
    if (tid < 256)
        pa = *(const float4*)&emb[(size_t)(row0 + a_r) * EMB + a_kq];
    else if (tid < 384)
        pb = *(const float4*)&Wx_w[(size_t)(col0 + b_c) * EMB + b_kq];

    for (int k0 = 0; k0 < EMB; k0 += 8) {
        __syncthreads();
        if (tid < 256) {
            As2[a_kq + 0][a_r] = dup2(pa.x);
            As2[a_kq + 1][a_r] = dup2(pa.y);
            As2[a_kq + 2][a_r] = dup2(pa.z);
            As2[a_kq + 3][a_r] = dup2(pa.w);
        } else if (tid < 384) {
            Bs[b_kq + 0][b_c] = pb.x;
            Bs[b_kq + 1][b_c] = pb.y;
            Bs[b_kq + 2][b_c] = pb.z;
            Bs[b_kq + 3][b_c] = pb.w;
        }
        __syncthreads();

        if (k0 + 8 < EMB) {
            if (tid < 256)
                pa = *(const float4*)&emb[(size_t)(row0 + a_r) * EMB + k0 + 8 + a_kq];
            else if (tid < 384)
                pb = *(const float4*)&Wx_w[(size_t)(col0 + b_c) * EMB + k0 + 8 + b_kq];
        }

#pragma unroll
        for (int k = 0; k < 8; k++) {
            ulonglong2 aA = *(const ulonglong2*)&As2[k][ty * 4];
            ulonglong2 aB = *(const ulonglong2*)&As2[k][ty * 4 + 2];
            float4 bv = *(const float4*)&Bs[k][tx * 4];
            unsigned long long bp0 = pk2(bv.x, bv.y);
            unsigned long long bp1 = pk2(bv.z, bv.w);
            fma2(acc[0][0], aA.x, bp0); fma2(acc[0][1], aA.x, bp1);
            fma2(acc[1][0], aA.y, bp0); fma2(acc[1][1], aA.y, bp1);
            fma2(acc[2][0], aB.x, bp0); fma2(acc[2][1], aB.x, bp1);
            fma2(acc[3][0], aB.y, bp0); fma2(acc[3][1], aB.y, bp1);
        }
    }

    float4 bx = *(const float4*)&Wx_b[col0 + tx * 4];
    float4 bh = *(const float4*)&Wh_b[col0 + tx * 4];
#pragma unroll
    for (int i = 0; i < 4; i++) {
        int m = row0 + ty * 4 + i;
        float v0, v1, v2, v3;
        upk2(acc[i][0], v0, v1);
        upk2(acc[i][1], v2, v3);
        float4 res = make_float4(v0 + bx.x + bh.x, v1 + bx.y + bh.y,
                                 v2 + bx.z + bh.z, v3 + bx.w + bh.w);
        *(float4*)&g_table[(size_t)m * HID + col0 + tx * 4] = res;
    }
}

// ---------------------------------------------------------------------------
// Cluster scan v4 (= round-8 v3 + phase C folded into phase B).
// 16 clusters x 8 CTAs, 512 threads. CTA = 64 j x 4 b.
// ---------------------------------------------------------------------------
#define SH_OFF_F      (131072 / 4)
#define SRP_OFF_U64   ((131072 + 16384) / 8)
#define SIDX_OFF_B    (131072 + 16384 + 16384)
#define SCAN_SMEM_BYTES (131072 + 16384 + 16384 + 8192)

#define SRP_IDX(ks, bp, jj, jp) ((((ks) * 4) + ((bp) * 2) + (jj)) * 32 + (jp))

__global__ __launch_bounds__(512, 1) __cluster_dims__(8, 1, 1)
void scan_kernel(const int* __restrict__ q, const int* __restrict__ r,
                 const float* __restrict__ Wh_w,
                 const float* __restrict__ tau) {
    extern __shared__ char smem_raw[];
    unsigned long long* swp   = (unsigned long long*)smem_raw;        // [512k][32jp]
    float*              shf   = (float*)smem_raw + SH_OFF_F;          // [2][512][4b]
    unsigned long long* srp   = (unsigned long long*)smem_raw + SRP_OFF_U64;
    int*                sidxm = (int*)(smem_raw + SIDX_OFF_B);        // [4b][512s]

    cg::cluster_group cluster = cg::this_cluster();
    const int rank = (int)cluster.block_rank();
    const int cid  = blockIdx.x >> 3;
    const int tid  = threadIdx.x;
    const int j0   = rank * 64;
    const int b0   = cid * 4;

    // ---- stage idx table ----
    for (int i = tid; i < 4 * SEQ; i += 512) {
        int b = i >> 9, s = i & 511;
        int m = (b0 + b) * SEQ + s;
        sidxm[i] = q[m] + NUM_C * r[m];
    }
    // ---- zero h buffer 0 ----
    for (int i = tid; i < 2048; i += 512) shf[i] = 0.0f;

    // ---- phase A mapping + stage weights paired ----
    const int jp = tid & 31;
    const int ks = tid >> 5;
    {
        const float* r0 = Wh_w + (size_t)(j0 + 2 * jp)     * HID + ks * 32;
        const float* r1 = Wh_w + (size_t)(j0 + 2 * jp + 1) * HID + ks * 32;
#pragma unroll
        for (int t = 0; t < 8; t++) {
            float4 f0 = *(const float4*)(r0 + t * 4);
            float4 f1 = *(const float4*)(r1 + t * 4);
            int kb = ks * 32 + t * 4;
            swp[(kb + 0) * 32 + jp] = pk2(f0.x, f1.x);
            swp[(kb + 1) * 32 + jp] = pk2(f0.y, f1.y);
            swp[(kb + 2) * 32 + jp] = pk2(f0.z, f1.z);
            swp[(kb + 3) * 32 + jp] = pk2(f0.w, f1.w);
        }
    }

    // ---- phase B mapping ----
    const int jB = tid & 63;
    const int bp = (tid >> 6) & 1;
    float itb = 1.0f;
    if (tid < 128) itb = 1.0f / tau[j0 + jB];

    __syncthreads();
    cluster.sync();

    // pre-load xp for s = 0
    float xp0 = 0.f, xp1 = 0.f;
    if (tid < 128) {
        int row0i = sidxm[(2 * bp) * SEQ + 0];
        int row1i = sidxm[(2 * bp + 1) * SEQ + 0];
        xp0 = __ldcg(&g_table[(size_t)row0i * HID + j0 + jB]);
        xp1 = __ldcg(&g_table[(size_t)row1i * HID + j0 + jB]);
    }

    for (int s = 0; s < SEQ; s++) {
        if (s) CLUSTER_WAIT();

        const float* shc = shf + (s & 1) * 2048;
        float*       shn = shf + ((s + 1) & 1) * 2048;

        float hold0 = 0.f, hold1 = 0.f;
        if (tid < 128) {
            float2 hf = *(const float2*)&shc[(j0 + jB) * 4 + 2 * bp];
            hold0 = hf.x; hold1 = hf.y;
        }

        // ---- phase A: 32 k per thread ----
        unsigned long long a00 = 0ull, a01 = 0ull, a10 = 0ull, a11 = 0ull;
        const unsigned long long* wp  = swp + (size_t)ks * 32 * 32 + jp;
        const ulonglong2*         hpp = (const ulonglong2*)shc + ks * 32;
#pragma unroll
        for (int kk = 0; kk < 32; kk++) {
            unsigned long long wpair = wp[kk * 32];
            ulonglong2 hu = hpp[kk];
            unsigned long long w00, w11;
            dupsplit(wpair, w00, w11);
            fma2(a00, w00, hu.x);
            fma2(a01, w00, hu.y);
            fma2(a10, w11, hu.x);
            fma2(a11, w11, hu.y);
        }
        srp[SRP_IDX(ks, 0, 0, jp)] = a00;
        srp[SRP_IDX(ks, 1, 0, jp)] = a01;
        srp[SRP_IDX(ks, 0, 1, jp)] = a10;
        srp[SRP_IDX(ks, 1, 1, jp)] = a11;
        __syncthreads();

        // ---- phase B (tid<128): reduce, update, scatter local+remote ----
        float hn0 = 0.f, hn1 = 0.f;
        if (tid < 128) {
            const int jj  = jB & 1;
            const int jph = jB >> 1;
            unsigned long long sa = srp[SRP_IDX(0, bp, jj, jph)];
            unsigned long long sb = srp[SRP_IDX(1, bp, jj, jph)];
#pragma unroll
            for (int k2 = 2; k2 < 16; k2 += 2) {
                add2(sa, srp[SRP_IDX(k2,     bp, jj, jph)]);
                add2(sb, srp[SRP_IDX(k2 + 1, bp, jj, jph)]);
            }
            add2(sa, sb);
            float f0, f1;
            upk2(sa, f0, f1);
            float th0 = tanhf(f0 + xp0);
            float th1 = tanhf(f1 + xp1);
            hn0 = hold0 + (th0 - hold0) * itb;
            hn1 = hold1 + (th1 - hold1) * itb;

            float2* dst_local = (float2*)&shn[(j0 + jB) * 4 + 2 * bp];
            *dst_local = make_float2(hn0, hn1);
            if (s < SEQ - 1) {
#pragma unroll
                for (int rr = 0; rr < 8; rr++) {
                    if (rr == rank) continue;
                    float2* dst = cluster.map_shared_rank(dst_local, rr);
                    *dst = make_float2(hn0, hn1);
                }
            }
        }

        if (s < SEQ - 1) CLUSTER_ARRIVE();

        // ---- deferred global store + next-step xp prefetch (overlaps wait) ----
        if (tid < 128) {
            g_hs[((size_t)(b0 + 2 * bp)     * SEQ + s) * HID + j0 + jB] = hn0;
            g_hs[((size_t)(b0 + 2 * bp + 1) * SEQ + s) * HID + j0 + jB] = hn1;
            if (s < SEQ - 1) {
                int row0i = sidxm[(2 * bp) * SEQ + s + 1];
                int row1i = sidxm[(2 * bp + 1) * SEQ + s + 1];
                xp0 = __ldcg(&g_table[(size_t)row0i * HID + j0 + jB]);
                xp1 = __ldcg(&g_table[(size_t)row1i * HID + j0 + jB]);
            }
        }
    }
}

// ---------------------------------------------------------------------------
// Output GEMM + sigmoid v2: 512 threads, tile 128r x 64c, dup-A smem.
// ---------------------------------------------------------------------------
__global__ __launch_bounds__(512, 2)
void out_kernel(const float* __restrict__ Wo_w,
                const float* __restrict__ Wo_b,
                float* __restrict__ out) {
    __shared__ unsigned long long As2[8][128];   // dup'd a: (a,a)
    __shared__ float              Bs[8][64];

    const int tid  = threadIdx.x;
    const int row0 = blockIdx.y * 128;
    const int col0 = blockIdx.x * 64;

    const int tx = tid & 15;
    const int ty = tid >> 4;

    unsigned long long acc[4][2];
#pragma unroll
    for (int i = 0; i < 4; i++) { acc[i][0] = 0ull; acc[i][1] = 0ull; }

    const int a_r  = tid >> 1;
    const int a_kq = (tid & 1) * 4;
    const int b_c  = (tid - 256) >> 1;
    const int b_kq = (tid & 1) * 4;

    float4 pa = make_float4(0, 0, 0, 0), pb = make_float4(0, 0, 0, 0);
    if (tid < 256)
        pa = *(const float4*)&g_hs[(size_t)(row0 + a_r) * HID + a_kq];
    else if (tid < 384)
        pb = *(const float4*)&Wo_w[(size_t)(col0 + b_c) * HID + b_kq];

    for (int k0 = 0; k0 < HID; k0 += 8) {
        __syncthreads();
        if (tid < 256) {
            As2[a_kq + 0][a_r] = dup2(pa.x);
            As2[a_kq + 1][a_r] = dup2(pa.y);
            As2[a_kq + 2][a_r] = dup2(pa.z);
            As2[a_kq + 3][a_r] = dup2(pa.w);
        } else if (tid < 384) {
            Bs[b_kq + 0][b_c] = pb.x;
            Bs[b_kq + 1][b_c] = pb.y;
            Bs[b_kq + 2][b_c] = pb.z;
            Bs[b_kq + 3][b_c] = pb.w;
        }
        __syncthreads();

        if (k0 + 8 < HID) {
            if (tid < 256)
                pa = *(const float4*)&g_hs[(size_t)(row0 + a_r) * HID + k0 + 8 + a_kq];
            else if (tid < 384)
                pb = *(const float4*)&Wo_w[(size_t)(col0 + b_c) * HID + k0 + 8 + b_kq];
        }

#pragma unroll
        for (int k = 0; k < 8; k++) {
            ulonglong2 aA = *(const ulonglong2*)&As2[k][ty * 4];
            ulonglong2 aB = *(const ulonglong2*)&As2[k][ty * 4 + 2];
            float4 bv = *(const float4*)&Bs[k][tx * 4];
            unsigned long long bp0 = pk2(bv.x, bv.y);
            unsigned long long bp1 = pk2(bv.z, bv.w);
            fma2(acc[0][0], aA.x, bp0); fma2(acc[0][1], aA.x, bp1);
            fma2(acc[1][0], aA.y, bp0); fma2(acc[1][1], aA.y, bp1);
            fma2(acc[2][0], aB.x, bp0); fma2(acc[2][1], aB.x, bp1);
            fma2(acc[3][0], aB.y, bp0); fma2(acc[3][1], aB.y, bp1);
        }
    }

    float4 bo = *(const float4*)&Wo_b[col0 + tx * 4];
#pragma unroll
    for (int i = 0; i < 4; i++) {
        int m = row0 + ty * 4 + i;
        float v0, v1, v2, v3;
        upk2(acc[i][0], v0, v1);
        upk2(acc[i][1], v2, v3);
        float l0 = v0 + bo.x, l1 = v1 + bo.y, l2 = v2 + bo.z, l3 = v3 + bo.w;
        float4 res = make_float4(1.0f / (1.0f + __expf(-l0)),
                                 1.0f / (1.0f + __expf(-l1)),
                                 1.0f / (1.0f + __expf(-l2)),
                                 1.0f / (1.0f + __expf(-l3)));
        *(float4*)&out[(size_t)m * NUM_C + col0 + tx * 4] = res;
    }
}

// ---------------------------------------------------------------------------
extern "C" void kernel_launch(void* const* d_in, const int* in_sizes, int n_in,
                              void* d_out, int out_size) {
    const int*   q    = (const int*)  d_in[0];
    const int*   r    = (const int*)  d_in[1];
    const float* emb  = (const float*)d_in[2];
    const float* Wh_w = (const float*)d_in[3];
    const float* Wh_b = (const float*)d_in[4];
    const float* Wx_w = (const float*)d_in[5];
    const float* Wx_b = (const float*)d_in[6];
    const float* tau  = (const float*)d_in[7];
    const float* Wo_w = (const float*)d_in[8];
    const float* Wo_b = (const float*)d_in[9];
    float*       out  = (float*)d_out;

    cudaFuncSetAttribute(scan_kernel,
                         cudaFuncAttributeMaxDynamicSharedMemorySize,
                         SCAN_SMEM_BYTES);

    // 1) projection table: 2048 x 512, 128 CTAs
    {
        dim3 grid(HID / 64, NROWS / 128);
        proj_kernel<<<grid, 512>>>(emb, Wx_w, Wx_b, Wh_b);
    }
    // 2) cluster scan: 128 CTAs = 16 clusters x 8 ranks
    scan_kernel<<<128, 512, SCAN_SMEM_BYTES>>>(q, r, Wh_w, tau);
    // 3) output GEMM + sigmoid: grid (16, 256) = 4096 CTAs
    {
        dim3 grid(NUM_C / 64, M_ROWS / 128);
        out_kernel<<<grid, 512>>>(Wo_w, Wo_b, out);
    }
}

// round 12
// speedup vs baseline: 1.5670x; 1.5670x over previous
#include <cuda_runtime.h>
#include <cuda_bf16.h>
#include <cooperative_groups.h>
#include <cstdint>

namespace cg = cooperative_groups;

#define NUM_C 1024
#define EMB   512
#define HID   512
#define BATCH 64
#define SEQ   512
#define M_ROWS (BATCH * SEQ)   // 32768
#define NROWS 2048             // distinct embedding rows

// ---------------------------------------------------------------------------
// Device scratch
// ---------------------------------------------------------------------------
__device__ float g_table[(size_t)NROWS * HID];    // 4 MB: emb@Wx^T + bx + bh
__device__ float g_hs   [(size_t)M_ROWS * HID];   // 64 MB: scan outputs

// ---------------------------------------------------------------------------
// f32x2 helpers
// ---------------------------------------------------------------------------
__device__ __forceinline__ void fma2(unsigned long long& acc,
                                     unsigned long long a, unsigned long long b) {
    asm("fma.rn.f32x2 %0, %1, %2, %0;" : "+l"(acc) : "l"(a), "l"(b));
}
__device__ __forceinline__ unsigned long long pk2(float lo, float hi) {
    unsigned long long r;
    asm("mov.b64 %0, {%1, %2};" : "=l"(r) : "f"(lo), "f"(hi));
    return r;
}
__device__ __forceinline__ unsigned long long dup2(float x) {
    unsigned long long r;
    asm("mov.b64 %0, {%1, %1};" : "=l"(r) : "f"(x));
    return r;
}
__device__ __forceinline__ void upk2(unsigned long long v, float& lo, float& hi) {
    asm("mov.b64 {%0, %1}, %2;" : "=f"(lo), "=f"(hi) : "l"(v));
}
__device__ __forceinline__ void add2(unsigned long long& acc, unsigned long long a) {
    asm("add.rn.f32x2 %0, %1, %2;" : "=l"(acc) : "l"(acc), "l"(a));
}
__device__ __forceinline__ void dupsplit(unsigned long long w,
                                         unsigned long long& a, unsigned long long& b) {
    asm("{\n\t.reg .b32 lo,hi;\n\t"
        "mov.b64 {lo,hi}, %2;\n\t"
        "mov.b64 %0, {lo,lo};\n\t"
        "mov.b64 %1, {hi,hi};\n\t}"
        : "=l"(a), "=l"(b) : "l"(w));
}

#define CLUSTER_ARRIVE() asm volatile("barrier.cluster.arrive.aligned;" ::: "memory")
#define CLUSTER_WAIT()   asm volatile("barrier.cluster.wait.aligned;"   ::: "memory")

// ---------------------------------------------------------------------------
// proj v2: table[m][n] = sum_e emb[m][e]*Wx_w[n][e] + Wx_b[n] + Wh_b[n]
// 512 threads, tile 128 x 64, grid (8,16) = 128 CTAs. (measured 56 us)
// ---------------------------------------------------------------------------
__global__ __launch_bounds__(512, 2)
void proj_kernel(const float* __restrict__ emb,
                 const float* __restrict__ Wx_w,
                 const float* __restrict__ Wx_b,
                 const float* __restrict__ Wh_b) {
    __shared__ unsigned long long As2[8][128];
    __shared__ float              Bs[8][64];

    const int tid  = threadIdx.x;
    const int row0 = blockIdx.y * 128;
    const int col0 = blockIdx.x * 64;

    const int tx = tid & 15;
    const int ty = tid >> 4;

    unsigned long long acc[4][2];
#pragma unroll
    for (int i = 0; i < 4; i++) { acc[i][0] = 0ull; acc[i][1] = 0ull; }

    const int a_r  = tid >> 1;
    const int a_kq = (tid & 1) * 4;
    const int b_c  = (tid - 256) >> 1;
    const int b_kq = (tid & 1) * 4;

    float4 pa = make_float4(0, 0, 0, 0), pb = make_float4(0, 0, 0, 0);
    if (tid < 256)
        pa = *(const float4*)&emb[(size_t)(row0 + a_r) * EMB + a_kq];
    else if (tid < 384)
        pb = *(const float4*)&Wx_w[(size_t)(col0 + b_c) * EMB + b_kq];

    for (int k0 = 0; k0 < EMB; k0 += 8) {
        __syncthreads();
        if (tid < 256) {
            As2[a_kq + 0][a_r] = dup2(pa.x);
            As2[a_kq + 1][a_r] = dup2(pa.y);
            As2[a_kq + 2][a_r] = dup2(pa.z);
            As2[a_kq + 3][a_r] = dup2(pa.w);
        } else if (tid < 384) {
            Bs[b_kq + 0][b_c] = pb.x;
            Bs[b_kq + 1][b_c] = pb.y;
            Bs[b_kq + 2][b_c] = pb.z;
            Bs[b_kq + 3][b_c] = pb.w;
        }
        __syncthreads();

        if (k0 + 8 < EMB) {
            if (tid < 256)
                pa = *(const float4*)&emb[(size_t)(row0 + a_r) * EMB + k0 + 8 + a_kq];
            else if (tid < 384)
                pb = *(const float4*)&Wx_w[(size_t)(col0 + b_c) * EMB + k0 + 8 + b_kq];
        }

#pragma unroll
        for (int k = 0; k < 8; k++) {
            ulonglong2 aA = *(const ulonglong2*)&As2[k][ty * 4];
            ulonglong2 aB = *(const ulonglong2*)&As2[k][ty * 4 + 2];
            float4 bv = *(const float4*)&Bs[k][tx * 4];
            unsigned long long bp0 = pk2(bv.x, bv.y);
            unsigned long long bp1 = pk2(bv.z, bv.w);
            fma2(acc[0][0], aA.x, bp0); fma2(acc[0][1], aA.x, bp1);
            fma2(acc[1][0], aA.y, bp0); fma2(acc[1][1], aA.y, bp1);
            fma2(acc[2][0], aB.x, bp0); fma2(acc[2][1], aB.x, bp1);
            fma2(acc[3][0], aB.y, bp0); fma2(acc[3][1], aB.y, bp1);
        }
    }

    float4 bx = *(const float4*)&Wx_b[col0 + tx * 4];
    float4 bh = *(const float4*)&Wh_b[col0 + tx * 4];
#pragma unroll
    for (int i = 0; i < 4; i++) {
        int m = row0 + ty * 4 + i;
        float v0, v1, v2, v3;
        upk2(acc[i][0], v0, v1);
        upk2(acc[i][1], v2, v3);
        float4 res = make_float4(v0 + bx.x + bh.x, v1 + bx.y + bh.y,
                                 v2 + bx.z + bh.z, v3 + bx.w + bh.w);
        *(float4*)&g_table[(size_t)m * HID + col0 + tx * 4] = res;
    }
}

// ---------------------------------------------------------------------------
// Cluster scan v6 = R8's v3 with weights moved from smem to REGISTERS.
// 16 clusters x 8 CTAs, 512 threads, __launch_bounds__(512,1) -> 128 regs.
// Thread (phase A): jp = tid&31 (j-pair), ks = tid>>5 (32-k slice).
// w2[32] u64 = 64 regs, total ~100 regs: no spills.
// Per k-iter: 1 broadcast LDS.128 + dupsplit + 4 FFMA2.
// Sync: split cluster barrier per step (R8, known-good).
// ---------------------------------------------------------------------------
// smem bytes: shf 2*512*16 = 16384 | srp 2048 u64 = 16384 | sidx 8192
#define SRP_OFF_U64   (16384 / 8)
#define SIDX_OFF_B    (16384 + 16384)
#define SCAN_SMEM_BYTES (16384 + 16384 + 8192)

#define SRP_IDX(ks, bp, jj, jp) ((((ks) * 4) + ((bp) * 2) + (jj)) * 32 + (jp))

__global__ __launch_bounds__(512, 1) __cluster_dims__(8, 1, 1)
void scan_kernel(const int* __restrict__ q, const int* __restrict__ r,
                 const float* __restrict__ Wh_w,
                 const float* __restrict__ tau) {
    extern __shared__ char smem_raw[];
    float*              shf   = (float*)smem_raw;                     // [2][512][4b]
    unsigned long long* srp   = (unsigned long long*)smem_raw + SRP_OFF_U64;
    int*                sidxm = (int*)(smem_raw + SIDX_OFF_B);        // [4b][512s]

    cg::cluster_group cluster = cg::this_cluster();
    const int rank = (int)cluster.block_rank();
    const int cid  = blockIdx.x >> 3;
    const int tid  = threadIdx.x;
    const int j0   = rank * 64;
    const int b0   = cid * 4;

    // ---- stage idx table ----
    for (int i = tid; i < 4 * SEQ; i += 512) {
        int b = i >> 9, s = i & 511;
        int m = (b0 + b) * SEQ + s;
        sidxm[i] = q[m] + NUM_C * r[m];
    }
    // ---- zero h buffer 0 ----
    for (int i = tid; i < 2048; i += 512) shf[i] = 0.0f;

    // ---- phase A mapping + REGISTER weights ----
    const int jp = tid & 31;            // j-pair -> j = 2jp, 2jp+1
    const int ks = tid >> 5;            // 0..15, 32 k each

    unsigned long long w2[32];          // 64 regs: (w_{2jp,k}, w_{2jp+1,k})
    {
        const float* r0 = Wh_w + (size_t)(j0 + 2 * jp)     * HID + ks * 32;
        const float* r1 = Wh_w + (size_t)(j0 + 2 * jp + 1) * HID + ks * 32;
#pragma unroll
        for (int t = 0; t < 8; t++) {
            float4 f0 = *(const float4*)(r0 + t * 4);
            float4 f1 = *(const float4*)(r1 + t * 4);
            w2[t * 4 + 0] = pk2(f0.x, f1.x);
            w2[t * 4 + 1] = pk2(f0.y, f1.y);
            w2[t * 4 + 2] = pk2(f0.z, f1.z);
            w2[t * 4 + 3] = pk2(f0.w, f1.w);
        }
    }

    // ---- phase B mapping ----
    const int jB = tid & 63;
    const int bp = (tid >> 6) & 1;
    float itb = 1.0f;
    if (tid < 128) itb = 1.0f / tau[j0 + jB];

    // ---- phase C mapping: 448 threads, one float4 each ----
    const int pc_rem = tid & 63;
    int pc_rk = tid >> 6;
    if (pc_rk >= rank) pc_rk += 1;

    __syncthreads();
    cluster.sync();

    // pre-load xp for s = 0
    float xp0 = 0.f, xp1 = 0.f;
    if (tid < 128) {
        int row0i = sidxm[(2 * bp) * SEQ + 0];
        int row1i = sidxm[(2 * bp + 1) * SEQ + 0];
        xp0 = __ldcg(&g_table[(size_t)row0i * HID + j0 + jB]);
        xp1 = __ldcg(&g_table[(size_t)row1i * HID + j0 + jB]);
    }

    for (int s = 0; s < SEQ; s++) {
        if (s) CLUSTER_WAIT();

        const float* shc = shf + (s & 1) * 2048;
        float*       shn = shf + ((s + 1) & 1) * 2048;

        float hold0 = 0.f, hold1 = 0.f;
        if (tid < 128) {
            float2 hf = *(const float2*)&shc[(j0 + jB) * 4 + 2 * bp];
            hold0 = hf.x; hold1 = hf.y;
        }

        // ---- phase A: 32 k per thread, weights in registers ----
        unsigned long long a00 = 0ull, a01 = 0ull, a10 = 0ull, a11 = 0ull;
        const ulonglong2* hpp = (const ulonglong2*)shc + ks * 32;
#pragma unroll
        for (int kk = 0; kk < 32; kk++) {
            ulonglong2 hu = hpp[kk];                      // broadcast 16B
            unsigned long long w00, w11;
            dupsplit(w2[kk], w00, w11);
            fma2(a00, w00, hu.x);
            fma2(a01, w00, hu.y);
            fma2(a10, w11, hu.x);
            fma2(a11, w11, hu.y);
        }
        srp[SRP_IDX(ks, 0, 0, jp)] = a00;
        srp[SRP_IDX(ks, 1, 0, jp)] = a01;
        srp[SRP_IDX(ks, 0, 1, jp)] = a10;
        srp[SRP_IDX(ks, 1, 1, jp)] = a11;
        __syncthreads();

        // ---- phase B (tid<128): reduce 16 slices, LTC update ----
        float hn0 = 0.f, hn1 = 0.f;
        if (tid < 128) {
            const int jj  = jB & 1;
            const int jph = jB >> 1;
            unsigned long long sa = srp[SRP_IDX(0, bp, jj, jph)];
            unsigned long long sb = srp[SRP_IDX(1, bp, jj, jph)];
#pragma unroll
            for (int k2 = 2; k2 < 16; k2 += 2) {
                add2(sa, srp[SRP_IDX(k2,     bp, jj, jph)]);
                add2(sb, srp[SRP_IDX(k2 + 1, bp, jj, jph)]);
            }
            add2(sa, sb);
            float f0, f1;
            upk2(sa, f0, f1);
            float th0 = tanhf(f0 + xp0);
            float th1 = tanhf(f1 + xp1);
            hn0 = hold0 + (th0 - hold0) * itb;
            hn1 = hold1 + (th1 - hold1) * itb;
            *(float2*)&shn[(j0 + jB) * 4 + 2 * bp] = make_float2(hn0, hn1);
        }
        __syncthreads();

        // ---- phase C: send own 1KB slice to 7 peers, then arrive ----
        if (s < SEQ - 1) {
            if (tid < 448) {
                float4* src = (float4*)(shn + j0 * 4) + pc_rem;
                float4  val = *src;
                float4* dst = cluster.map_shared_rank(src, pc_rk);
                *dst = val;
            }
            CLUSTER_ARRIVE();
        }

        // ---- deferred global store + next-step xp prefetch (overlaps wait) ----
        if (tid < 128) {
            g_hs[((size_t)(b0 + 2 * bp)     * SEQ + s) * HID + j0 + jB] = hn0;
            g_hs[((size_t)(b0 + 2 * bp + 1) * SEQ + s) * HID + j0 + jB] = hn1;
            if (s < SEQ - 1) {
                int row0i = sidxm[(2 * bp) * SEQ + s + 1];
                int row1i = sidxm[(2 * bp + 1) * SEQ + s + 1];
                xp0 = __ldcg(&g_table[(size_t)row0i * HID + j0 + jB]);
                xp1 = __ldcg(&g_table[(size_t)row1i * HID + j0 + jB]);
            }
        }
    }
}

// ---------------------------------------------------------------------------
// Output GEMM + sigmoid (R8 version: 256 threads, 128x128 tile, f32x2)
// ---------------------------------------------------------------------------
__global__ __launch_bounds__(256, 2)
void out_kernel(const float* __restrict__ Wo_w,
                const float* __restrict__ Wo_b,
                float* __restrict__ out) {
    __shared__ float As[8][128];
    __shared__ float Bs[8][128];

    const int tid  = threadIdx.x;
    const int row0 = blockIdx.y * 128;
    const int col0 = blockIdx.x * 128;

    const int lr = tid >> 1;
    const int lc = (tid & 1) * 4;
    const int tx = tid & 15;
    const int ty = tid >> 4;

    const float* aptr = g_hs + (size_t)(row0 + lr) * HID;
    const float* bptr = Wo_w + (size_t)(col0 + lr) * HID;

    unsigned long long accp[8][4];
#pragma unroll
    for (int i = 0; i < 8; i++)
#pragma unroll
        for (int j = 0; j < 4; j++) accp[i][j] = 0ull;

    float4 pa = *(const float4*)(aptr + lc);
    float4 pb = *(const float4*)(bptr + lc);

    for (int k0 = 0; k0 < HID; k0 += 8) {
        __syncthreads();
        As[lc + 0][lr] = pa.x; As[lc + 1][lr] = pa.y;
        As[lc + 2][lr] = pa.z; As[lc + 3][lr] = pa.w;
        Bs[lc + 0][lr] = pb.x; Bs[lc + 1][lr] = pb.y;
        Bs[lc + 2][lr] = pb.z; Bs[lc + 3][lr] = pb.w;
        __syncthreads();

        if (k0 + 8 < HID) {
            pa = *(const float4*)(aptr + k0 + 8 + lc);
            pb = *(const float4*)(bptr + k0 + 8 + lc);
        }

#pragma unroll
        for (int k = 0; k < 8; k++) {
            float4 a0 = *(const float4*)&As[k][ty * 8];
            float4 a1 = *(const float4*)&As[k][ty * 8 + 4];
            float4 b0 = *(const float4*)&Bs[k][tx * 8];
            float4 b1 = *(const float4*)&Bs[k][tx * 8 + 4];
            unsigned long long bp0 = pk2(b0.x, b0.y), bp1 = pk2(b0.z, b0.w);
            unsigned long long bp2 = pk2(b1.x, b1.y), bp3 = pk2(b1.z, b1.w);
            float av[8] = {a0.x, a0.y, a0.z, a0.w, a1.x, a1.y, a1.z, a1.w};
#pragma unroll
            for (int i = 0; i < 8; i++) {
                unsigned long long ad = dup2(av[i]);
                fma2(accp[i][0], ad, bp0);
                fma2(accp[i][1], ad, bp1);
                fma2(accp[i][2], ad, bp2);
                fma2(accp[i][3], ad, bp3);
            }
        }
    }

#pragma unroll
    for (int i = 0; i < 8; i++) {
        int m = row0 + ty * 8 + i;
        float* op = out + (size_t)m * NUM_C + col0 + tx * 8;
#pragma unroll
        for (int jp = 0; jp < 4; jp++) {
            float v0, v1;
            upk2(accp[i][jp], v0, v1);
            int n = col0 + tx * 8 + jp * 2;
            float l0 = v0 + Wo_b[n];
            float l1 = v1 + Wo_b[n + 1];
            op[jp * 2]     = 1.0f / (1.0f + __expf(-l0));
            op[jp * 2 + 1] = 1.0f / (1.0f + __expf(-l1));
        }
    }
}

// ---------------------------------------------------------------------------
extern "C" void kernel_launch(void* const* d_in, const int* in_sizes, int n_in,
                              void* d_out, int out_size) {
    const int*   q    = (const int*)  d_in[0];
    const int*   r    = (const int*)  d_in[1];
    const float* emb  = (const float*)d_in[2];
    const float* Wh_w = (const float*)d_in[3];
    const float* Wh_b = (const float*)d_in[4];
    const float* Wx_w = (const float*)d_in[5];
    const float* Wx_b = (const float*)d_in[6];
    const float* tau  = (const float*)d_in[7];
    const float* Wo_w = (const float*)d_in[8];
    const float* Wo_b = (const float*)d_in[9];
    float*       out  = (float*)d_out;

    cudaFuncSetAttribute(scan_kernel,
                         cudaFuncAttributeMaxDynamicSharedMemorySize,
                         SCAN_SMEM_BYTES);

    // 1) projection table: 2048 x 512, 128 CTAs (56 us measured)
    {
        dim3 grid(HID / 64, NROWS / 128);
        proj_kernel<<<grid, 512>>>(emb, Wx_w, Wx_b, Wh_b);
    }
    // 2) cluster scan (register weights): 128 CTAs = 16 clusters x 8 ranks
    scan_kernel<<<128, 512, SCAN_SMEM_BYTES>>>(q, r, Wh_w, tau);
    // 3) output GEMM + sigmoid
    {
        dim3 grid(NUM_C / 128, M_ROWS / 128);
        out_kernel<<<grid, 256>>>(Wo_w, Wo_b, out);
    }
}

// round 14
// speedup vs baseline: 1.5966x; 1.0189x over previous
#include <cuda_runtime.h>
#include <cuda_bf16.h>
#include <cooperative_groups.h>
#include <cstdint>

namespace cg = cooperative_groups;

#define NUM_C 1024
#define EMB   512
#define HID   512
#define BATCH 64
#define SEQ   512
#define M_ROWS (BATCH * SEQ)   // 32768
#define NROWS 2048             // distinct embedding rows

// ---------------------------------------------------------------------------
// Device scratch
// ---------------------------------------------------------------------------
__device__ float g_table[(size_t)NROWS * HID];    // 4 MB: emb@Wx^T + bx + bh
__device__ float g_hs   [(size_t)M_ROWS * HID];   // 64 MB: scan outputs

// ---------------------------------------------------------------------------
// f32x2 helpers
// ---------------------------------------------------------------------------
__device__ __forceinline__ void fma2(unsigned long long& acc,
                                     unsigned long long a, unsigned long long b) {
    asm("fma.rn.f32x2 %0, %1, %2, %0;" : "+l"(acc) : "l"(a), "l"(b));
}
__device__ __forceinline__ unsigned long long pk2(float lo, float hi) {
    unsigned long long r;
    asm("mov.b64 %0, {%1, %2};" : "=l"(r) : "f"(lo), "f"(hi));
    return r;
}
__device__ __forceinline__ unsigned long long dup2(float x) {
    unsigned long long r;
    asm("mov.b64 %0, {%1, %1};" : "=l"(r) : "f"(x));
    return r;
}
__device__ __forceinline__ void upk2(unsigned long long v, float& lo, float& hi) {
    asm("mov.b64 {%0, %1}, %2;" : "=f"(lo), "=f"(hi) : "l"(v));
}
__device__ __forceinline__ void add2(unsigned long long& acc, unsigned long long a) {
    asm("add.rn.f32x2 %0, %1, %2;" : "=l"(acc) : "l"(acc), "l"(a));
}
__device__ __forceinline__ void dupsplit(unsigned long long w,
                                         unsigned long long& a, unsigned long long& b) {
    asm("{\n\t.reg .b32 lo,hi;\n\t"
        "mov.b64 {lo,hi}, %2;\n\t"
        "mov.b64 %0, {lo,lo};\n\t"
        "mov.b64 %1, {hi,hi};\n\t}"
        : "=l"(a), "=l"(b) : "l"(w));
}

#define CLUSTER_ARRIVE() asm volatile("barrier.cluster.arrive.aligned;" ::: "memory")
#define CLUSTER_WAIT()   asm volatile("barrier.cluster.wait.aligned;"   ::: "memory")

// ---------------------------------------------------------------------------
// proj v2 (measured 57 us) — unchanged from R12
// ---------------------------------------------------------------------------
__global__ __launch_bounds__(512, 2)
void proj_kernel(const float* __restrict__ emb,
                 const float* __restrict__ Wx_w,
                 const float* __restrict__ Wx_b,
                 const float* __restrict__ Wh_b) {
    __shared__ unsigned long long As2[8][128];
    __shared__ float              Bs[8][64];

    const int tid  = threadIdx.x;
    const int row0 = blockIdx.y * 128;
    const int col0 = blockIdx.x * 64;
    const int tx = tid & 15;
    const int ty = tid >> 4;

    unsigned long long acc[4][2];
#pragma unroll
    for (int i = 0; i < 4; i++) { acc[i][0] = 0ull; acc[i][1] = 0ull; }

    const int a_r  = tid >> 1;
    const int a_kq = (tid & 1) * 4;
    const int b_c  = (tid - 256) >> 1;
    const int b_kq = (tid & 1) * 4;

    float4 pa = make_float4(0, 0, 0, 0), pb = make_float4(0, 0, 0, 0);
    if (tid < 256)
        pa = *(const float4*)&emb[(size_t)(row0 + a_r) * EMB + a_kq];
    else if (tid < 384)
        pb = *(const float4*)&Wx_w[(size_t)(col0 + b_c) * EMB + b_kq];

    for (int k0 = 0; k0 < EMB; k0 += 8) {
        __syncthreads();
        if (tid < 256) {
            As2[a_kq + 0][a_r] = dup2(pa.x);
            As2[a_kq + 1][a_r] = dup2(pa.y);
            As2[a_kq + 2][a_r] = dup2(pa.z);
            As2[a_kq + 3][a_r] = dup2(pa.w);
        } else if (tid < 384) {
            Bs[b_kq + 0][b_c] = pb.x;
            Bs[b_kq + 1][b_c] = pb.y;
            Bs[b_kq + 2][b_c] = pb.z;
            Bs[b_kq + 3][b_c] = pb.w;
        }
        __syncthreads();
        if (k0 + 8 < EMB) {
            if (tid < 256)
                pa = *(const float4*)&emb[(size_t)(row0 + a_r) * EMB + k0 + 8 + a_kq];
            else if (tid < 384)
                pb = *(const float4*)&Wx_w[(size_t)(col0 + b_c) * EMB + k0 + 8 + b_kq];
        }
#pragma unroll
        for (int k = 0; k < 8; k++) {
            ulonglong2 aA = *(const ulonglong2*)&As2[k][ty * 4];
            ulonglong2 aB = *(const ulonglong2*)&As2[k][ty * 4 + 2];
            float4 bv = *(const float4*)&Bs[k][tx * 4];
            unsigned long long bp0 = pk2(bv.x, bv.y);
            unsigned long long bp1 = pk2(bv.z, bv.w);
            fma2(acc[0][0], aA.x, bp0); fma2(acc[0][1], aA.x, bp1);
            fma2(acc[1][0], aA.y, bp0); fma2(acc[1][1], aA.y, bp1);
            fma2(acc[2][0], aB.x, bp0); fma2(acc[2][1], aB.x, bp1);
            fma2(acc[3][0], aB.y, bp0); fma2(acc[3][1], aB.y, bp1);
        }
    }

    float4 bx = *(const float4*)&Wx_b[col0 + tx * 4];
    float4 bh = *(const float4*)&Wh_b[col0 + tx * 4];
#pragma unroll
    for (int i = 0; i < 4; i++) {
        int m = row0 + ty * 4 + i;
        float v0, v1, v2, v3;
        upk2(acc[i][0], v0, v1);
        upk2(acc[i][1], v2, v3);
        float4 res = make_float4(v0 + bx.x + bh.x, v1 + bx.y + bh.y,
                                 v2 + bx.z + bh.z, v3 + bx.w + bh.w);
        *(float4*)&g_table[(size_t)m * HID + col0 + tx * 4] = res;
    }
}

// ---------------------------------------------------------------------------
// Cluster scan v6 (R12 WIN — byte-identical)
// ---------------------------------------------------------------------------
#define SRP_OFF_U64   (16384 / 8)
#define SIDX_OFF_B    (16384 + 16384)
#define SCAN_SMEM_BYTES (16384 + 16384 + 8192)
#define SRP_IDX(ks, bp, jj, jp) ((((ks) * 4) + ((bp) * 2) + (jj)) * 32 + (jp))

__global__ __launch_bounds__(512, 1) __cluster_dims__(8, 1, 1)
void scan_kernel(const int* __restrict__ q, const int* __restrict__ r,
                 const float* __restrict__ Wh_w,
                 const float* __restrict__ tau) {
    extern __shared__ char smem_raw[];
    float*              shf   = (float*)smem_raw;
    unsigned long long* srp   = (unsigned long long*)smem_raw + SRP_OFF_U64;
    int*                sidxm = (int*)(smem_raw + SIDX_OFF_B);

    cg::cluster_group cluster = cg::this_cluster();
    const int rank = (int)cluster.block_rank();
    const int cid  = blockIdx.x >> 3;
    const int tid  = threadIdx.x;
    const int j0   = rank * 64;
    const int b0   = cid * 4;

    for (int i = tid; i < 4 * SEQ; i += 512) {
        int b = i >> 9, s = i & 511;
        int m = (b0 + b) * SEQ + s;
        sidxm[i] = q[m] + NUM_C * r[m];
    }
    for (int i = tid; i < 2048; i += 512) shf[i] = 0.0f;

    const int jp = tid & 31;
    const int ks = tid >> 5;

    unsigned long long w2[32];
    {
        const float* r0 = Wh_w + (size_t)(j0 + 2 * jp)     * HID + ks * 32;
        const float* r1 = Wh_w + (size_t)(j0 + 2 * jp + 1) * HID + ks * 32;
#pragma unroll
        for (int t = 0; t < 8; t++) {
            float4 f0 = *(const float4*)(r0 + t * 4);
            float4 f1 = *(const float4*)(r1 + t * 4);
            w2[t * 4 + 0] = pk2(f0.x, f1.x);
            w2[t * 4 + 1] = pk2(f0.y, f1.y);
            w2[t * 4 + 2] = pk2(f0.z, f1.z);
            w2[t * 4 + 3] = pk2(f0.w, f1.w);
        }
    }

    const int jB = tid & 63;
    const int bp = (tid >> 6) & 1;
    float itb = 1.0f;
    if (tid < 128) itb = 1.0f / tau[j0 + jB];

    const int pc_rem = tid & 63;
    int pc_rk = tid >> 6;
    if (pc_rk >= rank) pc_rk += 1;

    __syncthreads();
    cluster.sync();

    float xp0 = 0.f, xp1 = 0.f;
    if (tid < 128) {
        int row0i = sidxm[(2 * bp) * SEQ + 0];
        int row1i = sidxm[(2 * bp + 1) * SEQ + 0];
        xp0 = __ldcg(&g_table[(size_t)row0i * HID + j0 + jB]);
        xp1 = __ldcg(&g_table[(size_t)row1i * HID + j0 + jB]);
    }

    for (int s = 0; s < SEQ; s++) {
        if (s) CLUSTER_WAIT();

        const float* shc = shf + (s & 1) * 2048;
        float*       shn = shf + ((s + 1) & 1) * 2048;

        float hold0 = 0.f, hold1 = 0.f;
        if (tid < 128) {
            float2 hf = *(const float2*)&shc[(j0 + jB) * 4 + 2 * bp];
            hold0 = hf.x; hold1 = hf.y;
        }

        unsigned long long a00 = 0ull, a01 = 0ull, a10 = 0ull, a11 = 0ull;
        const ulonglong2* hpp = (const ulonglong2*)shc + ks * 32;
#pragma unroll
        for (int kk = 0; kk < 32; kk++) {
            ulonglong2 hu = hpp[kk];
            unsigned long long w00, w11;
            dupsplit(w2[kk], w00, w11);
            fma2(a00, w00, hu.x);
            fma2(a01, w00, hu.y);
            fma2(a10, w11, hu.x);
            fma2(a11, w11, hu.y);
        }
        srp[SRP_IDX(ks, 0, 0, jp)] = a00;
        srp[SRP_IDX(ks, 1, 0, jp)] = a01;
        srp[SRP_IDX(ks, 0, 1, jp)] = a10;
        srp[SRP_IDX(ks, 1, 1, jp)] = a11;
        __syncthreads();

        float hn0 = 0.f, hn1 = 0.f;
        if (tid < 128) {
            const int jj  = jB & 1;
            const int jph = jB >> 1;
            unsigned long long sa = srp[SRP_IDX(0, bp, jj, jph)];
            unsigned long long sb = srp[SRP_IDX(1, bp, jj, jph)];
#pragma unroll
            for (int k2 = 2; k2 < 16; k2 += 2) {
                add2(sa, srp[SRP_IDX(k2,     bp, jj, jph)]);
                add2(sb, srp[SRP_IDX(k2 + 1, bp, jj, jph)]);
            }
            add2(sa, sb);
            float f0, f1;
            upk2(sa, f0, f1);
            float th0 = tanhf(f0 + xp0);
            float th1 = tanhf(f1 + xp1);
            hn0 = hold0 + (th0 - hold0) * itb;
            hn1 = hold1 + (th1 - hold1) * itb;
            *(float2*)&shn[(j0 + jB) * 4 + 2 * bp] = make_float2(hn0, hn1);
        }
        __syncthreads();

        if (s < SEQ - 1) {
            if (tid < 448) {
                float4* src = (float4*)(shn + j0 * 4) + pc_rem;
                float4  val = *src;
                float4* dst = cluster.map_shared_rank(src, pc_rk);
                *dst = val;
            }
            CLUSTER_ARRIVE();
        }

        if (tid < 128) {
            g_hs[((size_t)(b0 + 2 * bp)     * SEQ + s) * HID + j0 + jB] = hn0;
            g_hs[((size_t)(b0 + 2 * bp + 1) * SEQ + s) * HID + j0 + jB] = hn1;
            if (s < SEQ - 1) {
                int row0i = sidxm[(2 * bp) * SEQ + s + 1];
                int row1i = sidxm[(2 * bp + 1) * SEQ + s + 1];
                xp0 = __ldcg(&g_table[(size_t)row0i * HID + j0 + jB]);
                xp1 = __ldcg(&g_table[(size_t)row1i * HID + j0 + jB]);
            }
        }
    }
}

// ---------------------------------------------------------------------------
// out v4: 256 threads, 128x128 tile, BK=16, DOUBLE-BUFFERED smem ->
// one __syncthreads per K-chunk (32 barriers vs 128 in R12's version).
// ---------------------------------------------------------------------------
__global__ __launch_bounds__(256, 2)
void out_kernel(const float* __restrict__ Wo_w,
                const float* __restrict__ Wo_b,
                float* __restrict__ out) {
    __shared__ float As[2][16][128];
    __shared__ float Bs[2][16][128];

    const int tid  = threadIdx.x;
    const int row0 = blockIdx.y * 128;
    const int col0 = blockIdx.x * 128;

    const int lr = tid >> 1;          // 0..127 (row for A / col-row for B)
    const int lc = (tid & 1) * 8;     // k offset: 0 or 8 (two float4 each)
    const int tx = tid & 15;
    const int ty = tid >> 4;

    const float* aptr = g_hs + (size_t)(row0 + lr) * HID;
    const float* bptr = Wo_w + (size_t)(col0 + lr) * HID;

    unsigned long long accp[8][4];
#pragma unroll
    for (int i = 0; i < 8; i++)
#pragma unroll
        for (int j = 0; j < 4; j++) accp[i][j] = 0ull;

    // preload chunk 0 (16 k per chunk; each thread: 2 float4 of A, 2 of B)
    float4 pa0 = *(const float4*)(aptr + lc);
    float4 pa1 = *(const float4*)(aptr + lc + 4);
    float4 pb0 = *(const float4*)(bptr + lc);
    float4 pb1 = *(const float4*)(bptr + lc + 4);

    // store chunk 0 into buffer 0
    As[0][lc + 0][lr] = pa0.x; As[0][lc + 1][lr] = pa0.y;
    As[0][lc + 2][lr] = pa0.z; As[0][lc + 3][lr] = pa0.w;
    As[0][lc + 4][lr] = pa1.x; As[0][lc + 5][lr] = pa1.y;
    As[0][lc + 6][lr] = pa1.z; As[0][lc + 7][lr] = pa1.w;
    Bs[0][lc + 0][lr] = pb0.x; Bs[0][lc + 1][lr] = pb0.y;
    Bs[0][lc + 2][lr] = pb0.z; Bs[0][lc + 3][lr] = pb0.w;
    Bs[0][lc + 4][lr] = pb1.x; Bs[0][lc + 5][lr] = pb1.y;
    Bs[0][lc + 6][lr] = pb1.z; Bs[0][lc + 7][lr] = pb1.w;
    __syncthreads();

    for (int it = 0; it < 32; it++) {
        const int cur = it & 1;
        const int nxt = cur ^ 1;
        const bool more = (it + 1 < 32);

        // issue next chunk's global loads early (hidden by compute)
        if (more) {
            int k0 = (it + 1) * 16;
            pa0 = *(const float4*)(aptr + k0 + lc);
            pa1 = *(const float4*)(aptr + k0 + lc + 4);
            pb0 = *(const float4*)(bptr + k0 + lc);
            pb1 = *(const float4*)(bptr + k0 + lc + 4);
        }

        // compute current chunk (16 k)
#pragma unroll
        for (int k = 0; k < 16; k++) {
            float4 a0 = *(const float4*)&As[cur][k][ty * 8];
            float4 a1 = *(const float4*)&As[cur][k][ty * 8 + 4];
            float4 b0 = *(const float4*)&Bs[cur][k][tx * 8];
            float4 b1 = *(const float4*)&Bs[cur][k][tx * 8 + 4];
            unsigned long long bp0 = pk2(b0.x, b0.y), bp1 = pk2(b0.z, b0.w);
            unsigned long long bp2 = pk2(b1.x, b1.y), bp3 = pk2(b1.z, b1.w);
            float av[8] = {a0.x, a0.y, a0.z, a0.w, a1.x, a1.y, a1.z, a1.w};
#pragma unroll
            for (int i = 0; i < 8; i++) {
                unsigned long long ad = dup2(av[i]);
                fma2(accp[i][0], ad, bp0);
                fma2(accp[i][1], ad, bp1);
                fma2(accp[i][2], ad, bp2);
                fma2(accp[i][3], ad, bp3);
            }
        }

        // write next chunk into the other buffer, then single barrier
        if (more) {
            As[nxt][lc + 0][lr] = pa0.x; As[nxt][lc + 1][lr] = pa0.y;
            As[nxt][lc + 2][lr] = pa0.z; As[nxt][lc + 3][lr] = pa0.w;
            As[nxt][lc + 4][lr] = pa1.x; As[nxt][lc + 5][lr] = pa1.y;
            As[nxt][lc + 6][lr] = pa1.z; As[nxt][lc + 7][lr] = pa1.w;
            Bs[nxt][lc + 0][lr] = pb0.x; Bs[nxt][lc + 1][lr] = pb0.y;
            Bs[nxt][lc + 2][lr] = pb0.z; Bs[nxt][lc + 3][lr] = pb0.w;
            Bs[nxt][lc + 4][lr] = pb1.x; Bs[nxt][lc + 5][lr] = pb1.y;
            Bs[nxt][lc + 6][lr] = pb1.z; Bs[nxt][lc + 7][lr] = pb1.w;
            __syncthreads();
        }
    }

#pragma unroll
    for (int i = 0; i < 8; i++) {
        int m = row0 + ty * 8 + i;
        float* op = out + (size_t)m * NUM_C + col0 + tx * 8;
#pragma unroll
        for (int jp = 0; jp < 4; jp++) {
            float v0, v1;
            upk2(accp[i][jp], v0, v1);
            int n = col0 + tx * 8 + jp * 2;
            float l0 = v0 + Wo_b[n];
            float l1 = v1 + Wo_b[n + 1];
            op[jp * 2]     = 1.0f / (1.0f + __expf(-l0));
            op[jp * 2 + 1] = 1.0f / (1.0f + __expf(-l1));
        }
    }
}

// ---------------------------------------------------------------------------
extern "C" void kernel_launch(void* const* d_in, const int* in_sizes, int n_in,
                              void* d_out, int out_size) {
    const int*   q    = (const int*)  d_in[0];
    const int*   r    = (const int*)  d_in[1];
    const float* emb  = (const float*)d_in[2];
    const float* Wh_w = (const float*)d_in[3];
    const float* Wh_b = (const float*)d_in[4];
    const float* Wx_w = (const float*)d_in[5];
    const float* Wx_b = (const float*)d_in[6];
    const float* tau  = (const float*)d_in[7];
    const float* Wo_w = (const float*)d_in[8];
    const float* Wo_b = (const float*)d_in[9];
    float*       out  = (float*)d_out;

    cudaFuncSetAttribute(scan_kernel,
                         cudaFuncAttributeMaxDynamicSharedMemorySize,
                         SCAN_SMEM_BYTES);

    // 1) projection table: 2048 x 512, 128 CTAs (57 us measured)
    {
        dim3 grid(HID / 64, NROWS / 128);
        proj_kernel<<<grid, 512>>>(emb, Wx_w, Wx_b, Wh_b);
    }
    // 2) cluster scan (register weights, R12 WIN)
    scan_kernel<<<128, 512, SCAN_SMEM_BYTES>>>(q, r, Wh_w, tau);
    // 3) output GEMM + sigmoid (double-buffered, BK=16)
    {
        dim3 grid(NUM_C / 128, M_ROWS / 128);
        out_kernel<<<grid, 256>>>(Wo_w, Wo_b, out);
    }
}